// round 14
// baseline (speedup 1.0000x reference)
#include <cuda_runtime.h>
#include <mma.h>
#include <math.h>
#include <cstdint>

using namespace nvcuda;

#define NN 100000
#define NN_PAD 100096
#define NE 400000
#define NG 4096
#define RT128 782            // ceil(NN/128)
#define NEA 500096           // (NE + NN) padded to 128 multiple; 3907*128
#define RTEA 3907
#define SCAN_NB 98

typedef unsigned long long u64;

__device__ __forceinline__ u64 pack2(float x, float y) {
    u64 r; asm("mov.b64 %0,{%1,%2};" : "=l"(r) : "f"(x), "f"(y)); return r;
}
__device__ __forceinline__ void unpack2(u64 v, float& x, float& y) {
    asm("mov.b64 {%0,%1},%2;" : "=f"(x), "=f"(y) : "l"(v));
}
__device__ __forceinline__ u64 ffma2(u64 a, u64 b, u64 c) {
    u64 d; asm("fma.rn.f32x2 %0,%1,%2,%3;" : "=l"(d) : "l"(a), "l"(b), "l"(c)); return d;
}
__device__ __forceinline__ u64 fadd2(u64 a, u64 b) {
    u64 d; asm("add.rn.f32x2 %0,%1,%2;" : "=l"(d) : "l"(a), "l"(b)); return d;
}

// ---------------- scratch (static __device__ — zero-initialized at load) ----------------
__device__ float g_xpad[(size_t)NN_PAD * 40];
__device__ float g_xl[(size_t)NN_PAD * 128];
__device__ float g_xr[(size_t)NN_PAD * 128];
__device__ float g_xres[(size_t)NN_PAD * 128];
__device__ float g_h[(size_t)NN_PAD * 128];
__device__ float g_htf[(size_t)NN_PAD * 128];
__device__ float g_eap[(size_t)NEA * 16];      // padded (edge|selfloop) attrs, tf32
__device__ float g_ee1[(size_t)NEA * 128];     // attr @ We1
__device__ float g_ee2[(size_t)NEA * 128];     // attr @ We2
__device__ float g_loopsum[(size_t)NN * 13];
__device__ float g_zero[128];                  // zero bias, never written
__device__ int   g_deg[NN];
__device__ int   g_cur[NN];
__device__ int   g_offs[NN + 1];
__device__ int2  g_es[NE];
__device__ u64   g_fa[128];
__device__ float g_gsum[(size_t)NG * 128];
__device__ int   g_gcnt[NG];

// ---------------- setup: pad x + degree + loopsum atomics ----------------
__global__ void setupdeg_kernel(const float* __restrict__ x,
                                const int* __restrict__ dst,
                                const float* __restrict__ ea) {
    int i = blockIdx.x * blockDim.x + threadIdx.x;
    if (i < NN_PAD * 40) {
        int r = i / 40, c = i - r * 40;
        float v;
        if (r < NN && c < 38)      v = wmma::__float_to_tf32(x[(size_t)r * 38 + c]);
        else if (c == 38)          v = 1.0f;
        else                       v = 0.0f;
        g_xpad[i] = v;
    }
    if (i < NE) atomicAdd(&g_deg[dst[i]], 1);
    if (i < NE * 13) {
        int e = i / 13, j = i - e * 13;
        atomicAdd(&g_loopsum[(size_t)dst[e] * 13 + j], ea[i]);
    }
}

// ---------------- fill padded attr matrix: edges + self-loop means ----------------
__global__ void fillea_kernel(const float* __restrict__ ea) {
    int i = blockIdx.x * blockDim.x + threadIdx.x;
    if (i >= NEA * 16) return;
    int r = i >> 4, c = i & 15;
    float v = 0.f;
    if (c < 13) {
        if (r < NE) {
            v = wmma::__float_to_tf32(ea[(size_t)r * 13 + c]);
        } else if (r < NE + NN) {
            int n = r - NE;
            float invdeg = 1.f / fmaxf((float)g_deg[n], 1.f);
            v = wmma::__float_to_tf32(g_loopsum[(size_t)n * 13 + c] * invdeg);
        }
    }
    g_eap[i] = v;
}

// ---------------- single-kernel scan (decoupled lookback) ----------------
__global__ void scan_kernel() {
    __shared__ int s[1024];
    __shared__ int sprefix;
    int b = blockIdx.x;
    int n = b * 1024 + threadIdx.x;
    int v = (n < NN) ? g_deg[n] : 0;
    s[threadIdx.x] = v;
    __syncthreads();
    for (int off = 1; off < 1024; off <<= 1) {
        int t = (threadIdx.x >= off) ? s[threadIdx.x - off] : 0;
        __syncthreads();
        s[threadIdx.x] += t;
        __syncthreads();
    }
    if (threadIdx.x == 0)
        atomicExch(&g_fa[b], ((u64)(unsigned)s[1023] << 1) | 1ull);
    if (threadIdx.x < 32) {
        int sum = 0;
        for (int p = threadIdx.x; p < b; p += 32) {
            u64 w;
            do { w = atomicAdd(&g_fa[p], 0ull); } while (!(w & 1ull));
            sum += (int)(w >> 1);
        }
#pragma unroll
        for (int o = 16; o > 0; o >>= 1) sum += __shfl_xor_sync(0xffffffffu, sum, o);
        if (threadIdx.x == 0) sprefix = sum;
    }
    __syncthreads();
    if (n < NN) g_offs[n] = sprefix + s[threadIdx.x] - v;
    if (b == 0 && threadIdx.x == 0) g_offs[NN] = NE;
}

// ---------------- tensor-core tf32 GEMM (128x64 tile); last-y branch = scatter ----------------
template <int K, int KPAD, int AROW, int ASTRIDE, int SCATTER_Y>
__global__ void __launch_bounds__(256, 3)
mm_tc(const float* __restrict__ A,
      const int* __restrict__ srcp, const int* __restrict__ dstp,
      const float* __restrict__ Wa, const float* __restrict__ ba, float* __restrict__ oa,
      const float* __restrict__ Wb, const float* __restrict__ bb, float* __restrict__ ob,
      const float* __restrict__ Wc, const float* __restrict__ bc, float* __restrict__ oc) {
    if (SCATTER_Y >= 0 && blockIdx.y == SCATTER_Y) {
        int t = blockIdx.x * 256 + threadIdx.x;
#pragma unroll
        for (int rep = 0; rep < 2; ++rep) {
            int e = t + rep * (RT128 * 256);
            if (e < NE) {
                int node = dstp[e];
                int pos = g_offs[node] + atomicAdd(&g_cur[node], 1);
                g_es[pos] = make_int2(e, srcp[e]);
            }
        }
        return;
    }

    constexpr int WSTRIDE = 68;
    extern __shared__ float sm[];
    float* Wt = sm;
    float* At = sm + KPAD * WSTRIDE;

    int set = blockIdx.y >> 1;
    int ch  = blockIdx.y & 1;
    const float* W = (set == 0) ? Wa : (set == 1) ? Wb : Wc;
    const float* b = (set == 0) ? ba : (set == 1) ? bb : bc;
    float* out     = (set == 0) ? oa : (set == 1) ? ob : oc;

    int row0 = blockIdx.x * 128;

    {
        constexpr int SEGS = AROW / 4;
        for (int i = threadIdx.x; i < 128 * SEGS; i += 256) {
            int r = i / SEGS, seg = i - r * SEGS;
            unsigned d = (unsigned)__cvta_generic_to_shared(At + r * ASTRIDE + seg * 4);
            const float* s = A + (size_t)(row0 + r) * AROW + seg * 4;
            asm volatile("cp.async.cg.shared.global [%0], [%1], 16;" :: "r"(d), "l"(s));
        }
        asm volatile("cp.async.commit_group;");
    }
    for (int i = threadIdx.x; i < KPAD * 64; i += 256) {
        int k = i >> 6, c = i & 63;
        float v = (k < K) ? W[(size_t)k * 128 + ch * 64 + c]
                          : ((k == K) ? b[ch * 64 + c] : 0.f);
        Wt[k * WSTRIDE + c] = wmma::__float_to_tf32(v);
    }
    if (KPAD > AROW) {
        constexpr int TAIL = (KPAD > AROW) ? (KPAD - AROW) : 1;
        for (int i = threadIdx.x; i < 128 * TAIL; i += 256) {
            int r = i / TAIL, c = AROW + (i - r * TAIL);
            At[r * ASTRIDE + c] = (c == AROW) ? 1.0f : 0.f;
        }
    }
    asm volatile("cp.async.wait_group 0;");
    __syncthreads();

    int warp = threadIdx.x >> 5;
    int wr = warp >> 1;
    int wc = warp & 1;

    wmma::fragment<wmma::accumulator, 16, 16, 8, float> acc[2][2];
#pragma unroll
    for (int i = 0; i < 2; ++i)
#pragma unroll
        for (int j = 0; j < 2; ++j) wmma::fill_fragment(acc[i][j], 0.f);

#pragma unroll
    for (int kk = 0; kk < KPAD / 8; ++kk) {
        wmma::fragment<wmma::matrix_a, 16, 16, 8, wmma::precision::tf32,
                       wmma::row_major> af[2];
#pragma unroll
        for (int i = 0; i < 2; ++i)
            wmma::load_matrix_sync(af[i],
                At + (wr * 32 + i * 16) * ASTRIDE + kk * 8, ASTRIDE);
        wmma::fragment<wmma::matrix_b, 16, 16, 8, wmma::precision::tf32,
                       wmma::row_major> bf[2];
#pragma unroll
        for (int j = 0; j < 2; ++j)
            wmma::load_matrix_sync(bf[j],
                Wt + kk * 8 * WSTRIDE + wc * 32 + j * 16, WSTRIDE);
#pragma unroll
        for (int i = 0; i < 2; ++i)
#pragma unroll
            for (int j = 0; j < 2; ++j)
                wmma::mma_sync(acc[i][j], af[i], bf[j], acc[i][j]);
    }
#pragma unroll
    for (int i = 0; i < 2; ++i)
#pragma unroll
        for (int j = 0; j < 2; ++j)
            wmma::store_matrix_sync(
                out + (size_t)(row0 + wr * 32 + i * 16) * 128 + ch * 64 + wc * 32 + j * 16,
                acc[i][j], 128, wmma::mem_row_major);
}

// ---------------- per-edge update with precomputed ee vector ----------------
__device__ __forceinline__ void edge_upd(
    float4 xls, float4 eev, u64 xr01, u64 xr23, float4 att4,
    float& ss, u64& a01, u64& a23)
{
    u64 xl01 = pack2(xls.x, xls.y), xl23 = pack2(xls.z, xls.w);
    u64 z01 = fadd2(fadd2(xl01, xr01), pack2(eev.x, eev.y));
    u64 z23 = fadd2(fadd2(xl23, xr23), pack2(eev.z, eev.w));
    float z0, z1, z2, z3;
    unpack2(z01, z0, z1);
    unpack2(z23, z2, z3);
    z0 = fmaxf(z0, 0.2f * z0);
    z1 = fmaxf(z1, 0.2f * z1);
    z2 = fmaxf(z2, 0.2f * z2);
    z3 = fmaxf(z3, 0.2f * z3);
    float p = z0 * att4.x + z1 * att4.y + z2 * att4.z + z3 * att4.w;
    p += __shfl_xor_sync(0xffffffffu, p, 1);
    p += __shfl_xor_sync(0xffffffffu, p, 2);
    p += __shfl_xor_sync(0xffffffffu, p, 4);
    float ex = __expf(p);
    ss += ex;
    u64 ex2 = pack2(ex, ex);
    a01 = ffma2(ex2, xl01, a01);
    a23 = ffma2(ex2, xl23, a23);
}

// ---------------- fused GATv2: gather + exp-sum + ELU + residual + LN (+pool) ----------------
template <bool BLOCK2>
__global__ void __launch_bounds__(256)
gat_kernel(const float* __restrict__ xl, const float* __restrict__ xr,
           const float* __restrict__ ee,
           const float* __restrict__ resid, float* __restrict__ hout,
           float* __restrict__ houttf,
           const float* __restrict__ att, const float* __restrict__ ab,
           const float* __restrict__ lng, const float* __restrict__ lnb,
           const int* __restrict__ batch) {
    int lane = threadIdx.x & 31;
    int warp = threadIdx.x >> 5;
    int wid = blockIdx.x * 8 + warp;
    int nwarps = gridDim.x * 8;

    float4 att4 = ((const float4*)att)[lane];
    float4 ab4  = ((const float4*)ab)[lane];
    float4 lg4  = ((const float4*)lng)[lane];
    float4 lb4  = ((const float4*)lnb)[lane];
    const float4* xl4 = (const float4*)xl;
    const float4* ee4 = (const float4*)ee;

    for (int n = wid; n < NN; n += nwarps) {
        int off0 = g_offs[n], off1 = g_offs[n + 1];
        float4 xr4 = ((const float4*)xr)[(size_t)n * 32 + lane];
        u64 xr01 = pack2(xr4.x, xr4.y), xr23 = pack2(xr4.z, xr4.w);

        float ssA = 0.f, ssB = 0.f;
        u64 aA01 = 0ull, aA23 = 0ull, aB01 = 0ull, aB23 = 0ull;

        int idx = off0;
        bool h0 = idx < off1, h1 = idx + 1 < off1;
        float4 x0, x1, E0, E1;
        if (h0) {
            int2 e = g_es[idx];
            x0 = xl4[(size_t)e.y * 32 + lane];
            E0 = ee4[(size_t)e.x * 32 + lane];
        }
        if (h1) {
            int2 e = g_es[idx + 1];
            x1 = xl4[(size_t)e.y * 32 + lane];
            E1 = ee4[(size_t)e.x * 32 + lane];
        }

        while (h0) {
            bool nh0 = idx + 2 < off1, nh1 = idx + 3 < off1;
            float4 nx0, nx1, nE0, nE1;
            if (nh0) {
                int2 e = g_es[idx + 2];
                nx0 = xl4[(size_t)e.y * 32 + lane];
                nE0 = ee4[(size_t)e.x * 32 + lane];
            }
            if (nh1) {
                int2 e = g_es[idx + 3];
                nx1 = xl4[(size_t)e.y * 32 + lane];
                nE1 = ee4[(size_t)e.x * 32 + lane];
            }

            edge_upd(x0, E0, xr01, xr23, att4, ssA, aA01, aA23);
            if (h1) edge_upd(x1, E1, xr01, xr23, att4, ssB, aB01, aB23);

            h0 = nh0; h1 = nh1;
            x0 = nx0; E0 = nE0;
            x1 = nx1; E1 = nE1;
            idx += 2;
        }

        float ss = ssA + ssB;
        u64 a01 = fadd2(aA01, aB01);
        u64 a23 = fadd2(aA23, aB23);

        // self loop: ee row NE + n, xl row n
        {
            float4 xls = xl4[(size_t)n * 32 + lane];
            float4 Es  = ee4[(size_t)(NE + n) * 32 + lane];
            edge_upd(xls, Es, xr01, xr23, att4, ss, a01, a23);
        }

        float a0, a1, a2, a3;
        unpack2(a01, a0, a1);
        unpack2(a23, a2, a3);
        float inv = 1.f / ss;
        float t0 = a0 * inv + ab4.x;
        float t1 = a1 * inv + ab4.y;
        float t2 = a2 * inv + ab4.z;
        float t3 = a3 * inv + ab4.w;
        t0 = t0 > 0.f ? t0 : expm1f(t0);
        t1 = t1 > 0.f ? t1 : expm1f(t1);
        t2 = t2 > 0.f ? t2 : expm1f(t2);
        t3 = t3 > 0.f ? t3 : expm1f(t3);
        float4 r4 = ((const float4*)resid)[(size_t)n * 32 + lane];
        t0 += r4.x; t1 += r4.y; t2 += r4.z; t3 += r4.w;
        float s1 = t0 + t1 + t2 + t3;
#pragma unroll
        for (int o = 1; o < 32; o <<= 1) s1 += __shfl_xor_sync(0xffffffffu, s1, o);
        float mu = s1 * (1.f / 128.f);
        float d0 = t0 - mu, d1 = t1 - mu, d2 = t2 - mu, d3 = t3 - mu;
        float s2 = d0 * d0 + d1 * d1 + d2 * d2 + d3 * d3;
#pragma unroll
        for (int o = 1; o < 32; o <<= 1) s2 += __shfl_xor_sync(0xffffffffu, s2, o);
        float rstd = rsqrtf(s2 * (1.f / 128.f) + 1e-5f);
        float o0 = d0 * rstd * lg4.x + lb4.x;
        float o1 = d1 * rstd * lg4.y + lb4.y;
        float o2 = d2 * rstd * lg4.z + lb4.z;
        float o3 = d3 * rstd * lg4.w + lb4.w;

        if (!BLOCK2) {
            ((float4*)hout)[(size_t)n * 32 + lane] = make_float4(o0, o1, o2, o3);
            ((float4*)houttf)[(size_t)n * 32 + lane] = make_float4(
                wmma::__float_to_tf32(o0), wmma::__float_to_tf32(o1),
                wmma::__float_to_tf32(o2), wmma::__float_to_tf32(o3));
        } else {
            int g = batch[n];
            float* gs = g_gsum + (size_t)g * 128 + lane * 4;
            atomicAdd(gs + 0, o0);
            atomicAdd(gs + 1, o1);
            atomicAdd(gs + 2, o2);
            atomicAdd(gs + 3, o3);
            if (lane == 0) atomicAdd(&g_gcnt[g], 1);
        }
    }
}

// ---------------- readout: warp per graph ----------------
__global__ void __launch_bounds__(256)
readout_kernel(const float* __restrict__ Wd1, const float* __restrict__ bd1,
               const float* __restrict__ Wd2, const float* __restrict__ bd2,
               float* __restrict__ out) {
    __shared__ float sm[8][128];
    int lane = threadIdx.x & 31;
    int warp = threadIdx.x >> 5;
    int g = blockIdx.x * 8 + warp;
    if (g >= NG) return;

    int cnt = g_gcnt[g];
    float inv = 1.f / fmaxf((float)cnt, 1.f);
    float4 m4 = ((const float4*)g_gsum)[(size_t)g * 32 + lane];
    sm[warp][lane * 4 + 0] = m4.x * inv;
    sm[warp][lane * 4 + 1] = m4.y * inv;
    sm[warp][lane * 4 + 2] = m4.z * inv;
    sm[warp][lane * 4 + 3] = m4.w * inv;
    __syncwarp();

    float h0 = bd1[lane], h1 = bd1[lane + 32];
#pragma unroll 4
    for (int d = 0; d < 128; ++d) {
        float md = sm[warp][d];
        h0 += md * Wd1[d * 64 + lane];
        h1 += md * Wd1[d * 64 + lane + 32];
    }
    h0 = fmaxf(h0, 0.f);
    h1 = fmaxf(h1, 0.f);
    float p = h0 * Wd2[lane] + h1 * Wd2[lane + 32];
#pragma unroll
    for (int o = 1; o < 32; o <<= 1) p += __shfl_xor_sync(0xffffffffu, p, o);
    if (lane == 0) out[g] = p + bd2[0];
}

// ---------------- cleanup: re-zero ALL mutable counters (grid covers NN*13) ----------------
__global__ void cleanup_kernel() {
    int i = blockIdx.x * blockDim.x + threadIdx.x;
    if (i < NN) { g_deg[i] = 0; g_cur[i] = 0; }
    if (i < NN * 13) g_loopsum[i] = 0.f;
    if (i < NG * 128) g_gsum[i] = 0.f;
    if (i < NG) g_gcnt[i] = 0;
    if (i < 128) g_fa[i] = 0ull;
}

// ---------------- launch ----------------
extern "C" void kernel_launch(void* const* d_in, const int* in_sizes, int n_in,
                              void* d_out, int out_size) {
    const float* x         = (const float*)d_in[0];
    const int*   edge_idx  = (const int*)d_in[1];
    const float* edge_attr = (const float*)d_in[2];
    const int*   batch     = (const int*)d_in[3];
    const float* Wl1 = (const float*)d_in[4];
    const float* bl1 = (const float*)d_in[5];
    const float* Wr1 = (const float*)d_in[6];
    const float* br1 = (const float*)d_in[7];
    const float* We1 = (const float*)d_in[8];
    const float* att1 = (const float*)d_in[9];
    const float* ab1 = (const float*)d_in[10];
    const float* lng1 = (const float*)d_in[11];
    const float* lnb1 = (const float*)d_in[12];
    const float* Wres = (const float*)d_in[13];
    const float* bres = (const float*)d_in[14];
    const float* Wl2 = (const float*)d_in[15];
    const float* bl2 = (const float*)d_in[16];
    const float* Wr2 = (const float*)d_in[17];
    const float* br2 = (const float*)d_in[18];
    const float* We2 = (const float*)d_in[19];
    const float* att2 = (const float*)d_in[20];
    const float* ab2 = (const float*)d_in[21];
    const float* lng2 = (const float*)d_in[22];
    const float* lnb2 = (const float*)d_in[23];
    const float* Wd1 = (const float*)d_in[24];
    const float* bd1 = (const float*)d_in[25];
    const float* Wd2 = (const float*)d_in[26];
    const float* bd2 = (const float*)d_in[27];
    float* out = (float*)d_out;

    const int* src = edge_idx;
    const int* dst = edge_idx + NE;

    float *p_xpad, *p_xl, *p_xr, *p_xres, *p_h, *p_htf, *p_eap, *p_ee1, *p_ee2, *p_zero;
    cudaGetSymbolAddress((void**)&p_xpad, g_xpad);
    cudaGetSymbolAddress((void**)&p_xl, g_xl);
    cudaGetSymbolAddress((void**)&p_xr, g_xr);
    cudaGetSymbolAddress((void**)&p_xres, g_xres);
    cudaGetSymbolAddress((void**)&p_h, g_h);
    cudaGetSymbolAddress((void**)&p_htf, g_htf);
    cudaGetSymbolAddress((void**)&p_eap, g_eap);
    cudaGetSymbolAddress((void**)&p_ee1, g_ee1);
    cudaGetSymbolAddress((void**)&p_ee2, g_ee2);
    cudaGetSymbolAddress((void**)&p_zero, g_zero);

    int smem1 = (40 * 68 + 128 * 44) * 4;     // 33408 B
    int smem2 = (136 * 68 + 128 * 140) * 4;   // 108672 B
    int smemE = (16 * 68 + 128 * 20) * 4;     // 14592 B
    cudaFuncSetAttribute((const void*)mm_tc<38, 40, 40, 44, 6>,
                         cudaFuncAttributeMaxDynamicSharedMemorySize, smem1);
    cudaFuncSetAttribute((const void*)mm_tc<128, 136, 128, 140, -1>,
                         cudaFuncAttributeMaxDynamicSharedMemorySize, smem2);
    cudaFuncSetAttribute((const void*)mm_tc<13, 16, 16, 20, -1>,
                         cudaFuncAttributeMaxDynamicSharedMemorySize, smemE);

    setupdeg_kernel<<<(NE * 13 + 255) / 256, 256>>>(x, dst, edge_attr);    // 1
    fillea_kernel<<<(NEA * 16 + 255) / 256, 256>>>(edge_attr);             // 2
    scan_kernel<<<SCAN_NB, 1024>>>();                                       // 3
    mm_tc<38, 40, 40, 44, 6><<<dim3(RT128, 7), 256, smem1>>>(               // 4 (+scatter)
        p_xpad, src, dst, Wl1, bl1, p_xl, Wr1, br1, p_xr, Wres, bres, p_xres);
    mm_tc<13, 16, 16, 20, -1><<<dim3(RTEA, 4), 256, smemE>>>(               // 5 (ee1+ee2)
        p_eap, nullptr, nullptr, We1, p_zero, p_ee1, We2, p_zero, p_ee2,
        We1, p_zero, p_ee1);
    gat_kernel<false><<<2048, 256>>>(p_xl, p_xr, p_ee1, p_xres, p_h, p_htf, // 6
                                     att1, ab1, lng1, lnb1, nullptr);
    mm_tc<128, 136, 128, 140, -1><<<dim3(RT128, 4), 256, smem2>>>(          // 7
        p_htf, nullptr, nullptr, Wl2, bl2, p_xl, Wr2, br2, p_xr, Wr2, br2, p_xr);
    gat_kernel<true><<<2048, 256>>>(p_xl, p_xr, p_ee2, p_h, nullptr, nullptr, // 8
                                    att2, ab2, lng2, lnb2, batch);
    readout_kernel<<<(NG + 7) / 8, 256>>>(Wd1, bd1, Wd2, bd2, out);         // 9
    cleanup_kernel<<<(NN * 13 + 255) / 256, 256>>>();                       // 10
}

// round 15
// speedup vs baseline: 1.0713x; 1.0713x over previous
#include <cuda_runtime.h>
#include <mma.h>
#include <math.h>
#include <cstdint>

using namespace nvcuda;

#define NN 100000
#define NN_PAD 100096
#define NE 400000
#define NG 4096
#define RT128 782           // ceil(NN/128); 782*128 == 100096
#define SCAN_NB 98          // ceil(NN/1024)

typedef unsigned long long u64;

__device__ __forceinline__ u64 pack2(float x, float y) {
    u64 r; asm("mov.b64 %0,{%1,%2};" : "=l"(r) : "f"(x), "f"(y)); return r;
}
__device__ __forceinline__ void unpack2(u64 v, float& x, float& y) {
    asm("mov.b64 {%0,%1},%2;" : "=f"(x), "=f"(y) : "l"(v));
}
__device__ __forceinline__ u64 ffma2(u64 a, u64 b, u64 c) {
    u64 d; asm("fma.rn.f32x2 %0,%1,%2,%3;" : "=l"(d) : "l"(a), "l"(b), "l"(c)); return d;
}
__device__ __forceinline__ u64 fadd2(u64 a, u64 b) {
    u64 d; asm("add.rn.f32x2 %0,%1,%2;" : "=l"(d) : "l"(a), "l"(b)); return d;
}

// ---------------- scratch (static __device__ — zero-initialized at load) ----------------
__device__ float g_xpad[(size_t)NN_PAD * 40];   // tf32-rounded x, ones col at 38
__device__ float g_xl[(size_t)NN_PAD * 128];
__device__ float g_xr[(size_t)NN_PAD * 128];
__device__ float g_xres[(size_t)NN_PAD * 128];
__device__ float g_h[(size_t)NN_PAD * 128];     // exact h (residual path)
__device__ float g_htf[(size_t)NN_PAD * 128];   // tf32-rounded h (GEMM2 A operand)
__device__ int   g_deg[NN];
__device__ int   g_cur[NN];
__device__ int   g_offs[NN + 1];
__device__ int2  g_es[NE];       // (edge id, src node)
__device__ u64   g_fa[128];      // decoupled scan word
__device__ float g_gsum[(size_t)NG * 128];
__device__ int   g_gcnt[NG];

// ---------------- setup: pad x (tf32, stride 40, ones col 38) + degree count ----------------
__global__ void setupdeg_kernel(const float* __restrict__ x,
                                const int* __restrict__ dst) {
    int i = blockIdx.x * blockDim.x + threadIdx.x;
    if (i < NN_PAD * 40) {
        int r = i / 40, c = i - r * 40;
        float v;
        if (r < NN && c < 38)      v = wmma::__float_to_tf32(x[(size_t)r * 38 + c]);
        else if (c == 38)          v = 1.0f;
        else                       v = 0.0f;
        g_xpad[i] = v;
    }
    if (i < NE) atomicAdd(&g_deg[dst[i]], 1);
}

// ---------------- single-kernel scan (decoupled lookback, 98 resident blocks) ----------------
__global__ void scan_kernel() {
    __shared__ int s[1024];
    __shared__ int sprefix;
    int b = blockIdx.x;
    int n = b * 1024 + threadIdx.x;
    int v = (n < NN) ? g_deg[n] : 0;
    s[threadIdx.x] = v;
    __syncthreads();
    for (int off = 1; off < 1024; off <<= 1) {
        int t = (threadIdx.x >= off) ? s[threadIdx.x - off] : 0;
        __syncthreads();
        s[threadIdx.x] += t;
        __syncthreads();
    }
    if (threadIdx.x == 0)
        atomicExch(&g_fa[b], ((u64)(unsigned)s[1023] << 1) | 1ull);
    if (threadIdx.x < 32) {
        int sum = 0;
        for (int p = threadIdx.x; p < b; p += 32) {
            u64 w;
            do { w = atomicAdd(&g_fa[p], 0ull); } while (!(w & 1ull));
            sum += (int)(w >> 1);
        }
#pragma unroll
        for (int o = 16; o > 0; o >>= 1) sum += __shfl_xor_sync(0xffffffffu, sum, o);
        if (threadIdx.x == 0) sprefix = sum;
    }
    __syncthreads();
    if (n < NN) g_offs[n] = sprefix + s[threadIdx.x] - v;
    if (b == 0 && threadIdx.x == 0) g_offs[NN] = NE;
}

// ---------------- tensor-core tf32 GEMM (128x64 tile); y==6 branch = scatter ----------------
template <int K, int KPAD, int AROW, int ASTRIDE, bool FUSE_SCATTER>
__global__ void __launch_bounds__(256, 3)
mm_tc(const float* __restrict__ A,
      const int* __restrict__ srcp, const int* __restrict__ dstp,
      const float* __restrict__ Wa, const float* __restrict__ ba, float* __restrict__ oa,
      const float* __restrict__ Wb, const float* __restrict__ bb, float* __restrict__ ob,
      const float* __restrict__ Wc, const float* __restrict__ bc, float* __restrict__ oc) {
    if (FUSE_SCATTER && blockIdx.y == 6) {
        int t = blockIdx.x * 256 + threadIdx.x;
#pragma unroll
        for (int rep = 0; rep < 2; ++rep) {
            int e = t + rep * (RT128 * 256);
            if (e < NE) {
                int node = dstp[e];
                int pos = g_offs[node] + atomicAdd(&g_cur[node], 1);
                g_es[pos] = make_int2(e, srcp[e]);
            }
        }
        return;
    }

    constexpr int WSTRIDE = 68;
    extern __shared__ float sm[];
    float* Wt = sm;
    float* At = sm + KPAD * WSTRIDE;

    int set = blockIdx.y >> 1;
    int ch  = blockIdx.y & 1;
    const float* W = (set == 0) ? Wa : (set == 1) ? Wb : Wc;
    const float* b = (set == 0) ? ba : (set == 1) ? bb : bc;
    float* out     = (set == 0) ? oa : (set == 1) ? ob : oc;

    int row0 = blockIdx.x * 128;

    {
        constexpr int SEGS = AROW / 4;
        for (int i = threadIdx.x; i < 128 * SEGS; i += 256) {
            int r = i / SEGS, seg = i - r * SEGS;
            unsigned d = (unsigned)__cvta_generic_to_shared(At + r * ASTRIDE + seg * 4);
            const float* s = A + (size_t)(row0 + r) * AROW + seg * 4;
            asm volatile("cp.async.cg.shared.global [%0], [%1], 16;" :: "r"(d), "l"(s));
        }
        asm volatile("cp.async.commit_group;");
    }
    for (int i = threadIdx.x; i < KPAD * 64; i += 256) {
        int k = i >> 6, c = i & 63;
        float v = (k < K) ? W[(size_t)k * 128 + ch * 64 + c]
                          : ((k == K) ? b[ch * 64 + c] : 0.f);
        Wt[k * WSTRIDE + c] = wmma::__float_to_tf32(v);
    }
    if (KPAD > AROW) {
        constexpr int TAIL = KPAD - AROW;
        for (int i = threadIdx.x; i < 128 * TAIL; i += 256) {
            int r = i / TAIL, c = AROW + (i - r * TAIL);
            At[r * ASTRIDE + c] = (c == AROW) ? 1.0f : 0.f;
        }
    }
    asm volatile("cp.async.wait_group 0;");
    __syncthreads();

    int warp = threadIdx.x >> 5;
    int wr = warp >> 1;
    int wc = warp & 1;

    wmma::fragment<wmma::accumulator, 16, 16, 8, float> acc[2][2];
#pragma unroll
    for (int i = 0; i < 2; ++i)
#pragma unroll
        for (int j = 0; j < 2; ++j) wmma::fill_fragment(acc[i][j], 0.f);

#pragma unroll
    for (int kk = 0; kk < KPAD / 8; ++kk) {
        wmma::fragment<wmma::matrix_a, 16, 16, 8, wmma::precision::tf32,
                       wmma::row_major> af[2];
#pragma unroll
        for (int i = 0; i < 2; ++i)
            wmma::load_matrix_sync(af[i],
                At + (wr * 32 + i * 16) * ASTRIDE + kk * 8, ASTRIDE);
        wmma::fragment<wmma::matrix_b, 16, 16, 8, wmma::precision::tf32,
                       wmma::row_major> bf[2];
#pragma unroll
        for (int j = 0; j < 2; ++j)
            wmma::load_matrix_sync(bf[j],
                Wt + kk * 8 * WSTRIDE + wc * 32 + j * 16, WSTRIDE);
#pragma unroll
        for (int i = 0; i < 2; ++i)
#pragma unroll
            for (int j = 0; j < 2; ++j)
                wmma::mma_sync(acc[i][j], af[i], bf[j], acc[i][j]);
    }
#pragma unroll
    for (int i = 0; i < 2; ++i)
#pragma unroll
        for (int j = 0; j < 2; ++j)
            wmma::store_matrix_sync(
                out + (size_t)(row0 + wr * 32 + i * 16) * 128 + ch * 64 + wc * 32 + j * 16,
                acc[i][j], 128, wmma::mem_row_major);
}

// ---------------- per-edge GATv2 update: exp-sum (no max; logits << 88) ----------------
__device__ __forceinline__ void edge_update(
    float v, const u64 (&Wp)[13][2], u64 xl01, u64 xl23, u64 xr01, u64 xr23,
    float4 att4, float& ss, u64& a01, u64& a23)
{
    u64 e01a = 0ull, e23a = 0ull, e01b = 0ull, e23b = 0ull;
#pragma unroll
    for (int j = 0; j < 13; j += 2) {
        float f = __shfl_sync(0xffffffffu, v, j);
        u64 ff = pack2(f, f);
        e01a = ffma2(ff, Wp[j][0], e01a);
        e23a = ffma2(ff, Wp[j][1], e23a);
    }
#pragma unroll
    for (int j = 1; j < 13; j += 2) {
        float f = __shfl_sync(0xffffffffu, v, j);
        u64 ff = pack2(f, f);
        e01b = ffma2(ff, Wp[j][0], e01b);
        e23b = ffma2(ff, Wp[j][1], e23b);
    }
    u64 z01 = fadd2(fadd2(xl01, xr01), fadd2(e01a, e01b));
    u64 z23 = fadd2(fadd2(xl23, xr23), fadd2(e23a, e23b));
    float z0, z1, z2, z3;
    unpack2(z01, z0, z1);
    unpack2(z23, z2, z3);
    z0 = fmaxf(z0, 0.2f * z0);
    z1 = fmaxf(z1, 0.2f * z1);
    z2 = fmaxf(z2, 0.2f * z2);
    z3 = fmaxf(z3, 0.2f * z3);
    float p = z0 * att4.x + z1 * att4.y + z2 * att4.z + z3 * att4.w;
    p += __shfl_xor_sync(0xffffffffu, p, 1);
    p += __shfl_xor_sync(0xffffffffu, p, 2);
    p += __shfl_xor_sync(0xffffffffu, p, 4);
    float ex = __expf(p);
    ss += ex;
    u64 ex2 = pack2(ex, ex);
    a01 = ffma2(ex2, xl01, a01);
    a23 = ffma2(ex2, xl23, a23);
}

// ---------------- fused GATv2: register-dieted, 3 blocks/SM ----------------
// Dual accumulator chains, no explicit prefetch (loads hoisted per pair),
// epilogue constants reloaded per node to cut persistent registers.
template <bool BLOCK2>
__global__ void __launch_bounds__(256, 3)
gat_kernel(const float* __restrict__ xl, const float* __restrict__ xr,
           const float* __restrict__ resid, float* __restrict__ hout,
           float* __restrict__ houttf,
           const float* __restrict__ We, const float* __restrict__ att,
           const float* __restrict__ ab, const float* __restrict__ lng,
           const float* __restrict__ lnb,
           const float* __restrict__ edge_attr, const int* __restrict__ batch) {
    int lane = threadIdx.x & 31;
    int warp = threadIdx.x >> 5;
    int wid = blockIdx.x * 8 + warp;
    int nwarps = gridDim.x * 8;

    u64 Wp[13][2];
#pragma unroll
    for (int j = 0; j < 13; ++j) {
        float4 w = *(const float4*)&We[j * 128 + lane * 4];
        Wp[j][0] = pack2(w.x, w.y);
        Wp[j][1] = pack2(w.z, w.w);
    }
    float4 att4 = ((const float4*)att)[lane];
    const float4* xl4 = (const float4*)xl;

    for (int n = wid; n < NN; n += nwarps) {
        int off0 = g_offs[n], off1 = g_offs[n + 1];
        float4 xr4 = ((const float4*)xr)[(size_t)n * 32 + lane];
        u64 xr01 = pack2(xr4.x, xr4.y), xr23 = pack2(xr4.z, xr4.w);
        float invdeg = 1.f / fmaxf((float)(off1 - off0), 1.f);

        float ssA = 0.f, ssB = 0.f;
        u64 aA01 = 0ull, aA23 = 0ull, aB01 = 0ull, aB23 = 0ull;
        float vsum = 0.f;

        int idx = off0;
        for (; idx + 1 < off1; idx += 2) {
            int2 e0 = g_es[idx];
            int2 e1 = g_es[idx + 1];
            float4 x0 = xl4[(size_t)e0.y * 32 + lane];
            float4 x1 = xl4[(size_t)e1.y * 32 + lane];
            float v0 = (lane < 13) ? edge_attr[(size_t)e0.x * 13 + lane] : 0.f;
            float v1 = (lane < 13) ? edge_attr[(size_t)e1.x * 13 + lane] : 0.f;
            vsum += v0 + v1;
            u64 x001 = pack2(x0.x, x0.y), x023 = pack2(x0.z, x0.w);
            edge_update(v0, Wp, x001, x023, xr01, xr23, att4, ssA, aA01, aA23);
            u64 x101 = pack2(x1.x, x1.y), x123 = pack2(x1.z, x1.w);
            edge_update(v1, Wp, x101, x123, xr01, xr23, att4, ssB, aB01, aB23);
        }
        if (idx < off1) {
            int2 e0 = g_es[idx];
            float4 x0 = xl4[(size_t)e0.y * 32 + lane];
            float v0 = (lane < 13) ? edge_attr[(size_t)e0.x * 13 + lane] : 0.f;
            vsum += v0;
            u64 x001 = pack2(x0.x, x0.y), x023 = pack2(x0.z, x0.w);
            edge_update(v0, Wp, x001, x023, xr01, xr23, att4, ssA, aA01, aA23);
        }

        float ss = ssA + ssB;
        u64 a01 = fadd2(aA01, aB01);
        u64 a23 = fadd2(aA23, aB23);

        // ---- self loop: attr = mean of in-edge attrs, src = n ----
        {
            float vL = vsum * invdeg;
            float4 xls = xl4[(size_t)n * 32 + lane];
            u64 xl01 = pack2(xls.x, xls.y), xl23 = pack2(xls.z, xls.w);
            edge_update(vL, Wp, xl01, xl23, xr01, xr23, att4, ss, a01, a23);
        }

        // ---- epilogue (constants reloaded here to keep loop registers low) ----
        float4 ab4 = ((const float4*)ab)[lane];
        float4 lg4 = ((const float4*)lng)[lane];
        float4 lb4 = ((const float4*)lnb)[lane];

        float a0, a1, a2, a3;
        unpack2(a01, a0, a1);
        unpack2(a23, a2, a3);
        float inv = 1.f / ss;
        float t0 = a0 * inv + ab4.x;
        float t1 = a1 * inv + ab4.y;
        float t2 = a2 * inv + ab4.z;
        float t3 = a3 * inv + ab4.w;
        t0 = t0 > 0.f ? t0 : expm1f(t0);
        t1 = t1 > 0.f ? t1 : expm1f(t1);
        t2 = t2 > 0.f ? t2 : expm1f(t2);
        t3 = t3 > 0.f ? t3 : expm1f(t3);
        float4 r4 = ((const float4*)resid)[(size_t)n * 32 + lane];
        t0 += r4.x; t1 += r4.y; t2 += r4.z; t3 += r4.w;
        float s1 = t0 + t1 + t2 + t3;
#pragma unroll
        for (int o = 1; o < 32; o <<= 1) s1 += __shfl_xor_sync(0xffffffffu, s1, o);
        float mu = s1 * (1.f / 128.f);
        float d0 = t0 - mu, d1 = t1 - mu, d2 = t2 - mu, d3 = t3 - mu;
        float s2 = d0 * d0 + d1 * d1 + d2 * d2 + d3 * d3;
#pragma unroll
        for (int o = 1; o < 32; o <<= 1) s2 += __shfl_xor_sync(0xffffffffu, s2, o);
        float rstd = rsqrtf(s2 * (1.f / 128.f) + 1e-5f);
        float o0 = d0 * rstd * lg4.x + lb4.x;
        float o1 = d1 * rstd * lg4.y + lb4.y;
        float o2 = d2 * rstd * lg4.z + lb4.z;
        float o3 = d3 * rstd * lg4.w + lb4.w;

        if (!BLOCK2) {
            ((float4*)hout)[(size_t)n * 32 + lane] = make_float4(o0, o1, o2, o3);
            ((float4*)houttf)[(size_t)n * 32 + lane] = make_float4(
                wmma::__float_to_tf32(o0), wmma::__float_to_tf32(o1),
                wmma::__float_to_tf32(o2), wmma::__float_to_tf32(o3));
        } else {
            int g = batch[n];
            float* gs = g_gsum + (size_t)g * 128 + lane * 4;
            atomicAdd(gs + 0, o0);
            atomicAdd(gs + 1, o1);
            atomicAdd(gs + 2, o2);
            atomicAdd(gs + 3, o3);
            if (lane == 0) atomicAdd(&g_gcnt[g], 1);
        }
    }
}

// ---------------- readout: warp per graph ----------------
__global__ void __launch_bounds__(256)
readout_kernel(const float* __restrict__ Wd1, const float* __restrict__ bd1,
               const float* __restrict__ Wd2, const float* __restrict__ bd2,
               float* __restrict__ out) {
    __shared__ float sm[8][128];
    int lane = threadIdx.x & 31;
    int warp = threadIdx.x >> 5;
    int g = blockIdx.x * 8 + warp;
    if (g >= NG) return;

    int cnt = g_gcnt[g];
    float inv = 1.f / fmaxf((float)cnt, 1.f);
    float4 m4 = ((const float4*)g_gsum)[(size_t)g * 32 + lane];
    sm[warp][lane * 4 + 0] = m4.x * inv;
    sm[warp][lane * 4 + 1] = m4.y * inv;
    sm[warp][lane * 4 + 2] = m4.z * inv;
    sm[warp][lane * 4 + 3] = m4.w * inv;
    __syncwarp();

    float h0 = bd1[lane], h1 = bd1[lane + 32];
#pragma unroll 4
    for (int d = 0; d < 128; ++d) {
        float md = sm[warp][d];
        h0 += md * Wd1[d * 64 + lane];
        h1 += md * Wd1[d * 64 + lane + 32];
    }
    h0 = fmaxf(h0, 0.f);
    h1 = fmaxf(h1, 0.f);
    float p = h0 * Wd2[lane] + h1 * Wd2[lane + 32];
#pragma unroll
    for (int o = 1; o < 32; o <<= 1) p += __shfl_xor_sync(0xffffffffu, p, o);
    if (lane == 0) out[g] = p + bd2[0];
}

// ---------------- cleanup: re-zero counters for next replay ----------------
__global__ void cleanup_kernel() {
    int i = blockIdx.x * blockDim.x + threadIdx.x;
    if (i < NN) { g_deg[i] = 0; g_cur[i] = 0; }
    if (i < NG * 128) g_gsum[i] = 0.f;
    if (i < NG) g_gcnt[i] = 0;
    if (i < 128) g_fa[i] = 0ull;
}

// ---------------- launch ----------------
extern "C" void kernel_launch(void* const* d_in, const int* in_sizes, int n_in,
                              void* d_out, int out_size) {
    const float* x         = (const float*)d_in[0];
    const int*   edge_idx  = (const int*)d_in[1];
    const float* edge_attr = (const float*)d_in[2];
    const int*   batch     = (const int*)d_in[3];
    const float* Wl1 = (const float*)d_in[4];
    const float* bl1 = (const float*)d_in[5];
    const float* Wr1 = (const float*)d_in[6];
    const float* br1 = (const float*)d_in[7];
    const float* We1 = (const float*)d_in[8];
    const float* att1 = (const float*)d_in[9];
    const float* ab1 = (const float*)d_in[10];
    const float* lng1 = (const float*)d_in[11];
    const float* lnb1 = (const float*)d_in[12];
    const float* Wres = (const float*)d_in[13];
    const float* bres = (const float*)d_in[14];
    const float* Wl2 = (const float*)d_in[15];
    const float* bl2 = (const float*)d_in[16];
    const float* Wr2 = (const float*)d_in[17];
    const float* br2 = (const float*)d_in[18];
    const float* We2 = (const float*)d_in[19];
    const float* att2 = (const float*)d_in[20];
    const float* ab2 = (const float*)d_in[21];
    const float* lng2 = (const float*)d_in[22];
    const float* lnb2 = (const float*)d_in[23];
    const float* Wd1 = (const float*)d_in[24];
    const float* bd1 = (const float*)d_in[25];
    const float* Wd2 = (const float*)d_in[26];
    const float* bd2 = (const float*)d_in[27];
    float* out = (float*)d_out;

    const int* src = edge_idx;
    const int* dst = edge_idx + NE;

    float *p_xpad, *p_xl, *p_xr, *p_xres, *p_h, *p_htf;
    cudaGetSymbolAddress((void**)&p_xpad, g_xpad);
    cudaGetSymbolAddress((void**)&p_xl, g_xl);
    cudaGetSymbolAddress((void**)&p_xr, g_xr);
    cudaGetSymbolAddress((void**)&p_xres, g_xres);
    cudaGetSymbolAddress((void**)&p_h, g_h);
    cudaGetSymbolAddress((void**)&p_htf, g_htf);

    int smem1 = (40 * 68 + 128 * 44) * 4;     // 33408 B
    int smem2 = (136 * 68 + 128 * 140) * 4;   // 108672 B
    cudaFuncSetAttribute((const void*)mm_tc<38, 40, 40, 44, true>,
                         cudaFuncAttributeMaxDynamicSharedMemorySize, smem1);
    cudaFuncSetAttribute((const void*)mm_tc<128, 136, 128, 140, false>,
                         cudaFuncAttributeMaxDynamicSharedMemorySize, smem2);

    setupdeg_kernel<<<(NN_PAD * 40 + 255) / 256, 256>>>(x, dst);          // 1
    scan_kernel<<<SCAN_NB, 1024>>>();                                      // 2
    mm_tc<38, 40, 40, 44, true><<<dim3(RT128, 7), 256, smem1>>>(           // 3 (+scatter)
        p_xpad, src, dst, Wl1, bl1, p_xl, Wr1, br1, p_xr, Wres, bres, p_xres);
    gat_kernel<false><<<2048, 256>>>(p_xl, p_xr, p_xres, p_h, p_htf,       // 4 (ncu slot)
                                     We1, att1, ab1, lng1, lnb1,
                                     edge_attr, nullptr);
    mm_tc<128, 136, 128, 140, false><<<dim3(RT128, 4), 256, smem2>>>(      // 5
        p_htf, nullptr, nullptr, Wl2, bl2, p_xl, Wr2, br2, p_xr, Wr2, br2, p_xr);
    gat_kernel<true><<<2048, 256>>>(p_xl, p_xr, p_h, nullptr, nullptr,     // 6
                                    We2, att2, ab2, lng2, lnb2,
                                    edge_attr, batch);
    readout_kernel<<<(NG + 7) / 8, 256>>>(Wd1, bd1, Wd2, bd2, out);        // 7
    cleanup_kernel<<<(NG * 128 + 255) / 256, 256>>>();                     // 8
}